// round 17
// baseline (speedup 1.0000x reference)
#include <cuda_runtime.h>

// ---------------------------------------------------------------------------
// EdgeNetwork: per-node factorization + 2 edges/thread (scalar math).
//   pre_k : xs[n] = center(x@W1a + b1 + vp[batch]@W1c); xb[n] = center(x@W1b)
//   edge_k: mean-free LN (centered weights), K-folded tanh, layer-3 rc-fold,
//           2-level software pipeline, LDG.256 gathers, persistent grid.
//   R17: pipelined loop manually unrolled x2 with ping-pong buffers --
//        rotation MOVs become compile-time register renaming.
// ---------------------------------------------------------------------------

#define NODE_CAP 131072
#define KLOG2E 2.8853900817779268f   // 2*log2(e)

__device__ __align__(32) float g_xs[NODE_CAP * 8];
__device__ __align__(32) float g_xb[NODE_CAP * 8];

__device__ __forceinline__ int detect_is64(const int* __restrict__ ei) {
    int nz = 0;
#pragma unroll
    for (int i = 1; i < 16; i += 2) nz |= ei[i];
    return nz == 0;
}

// 256-bit read-only global load (sm_100+): full 32B record in one LDG.
__device__ __forceinline__ void ldg256(const float* __restrict__ p,
                                       float4& a, float4& b) {
    asm("ld.global.nc.v8.f32 {%0,%1,%2,%3,%4,%5,%6,%7}, [%8];"
        : "=f"(a.x), "=f"(a.y), "=f"(a.z), "=f"(a.w),
          "=f"(b.x), "=f"(b.y), "=f"(b.z), "=f"(b.w)
        : "l"(p));
}

// ---------------------------------------------------------------------------
// Per-node precompute; xs/xb stored mean-centered (LN is shift-invariant).
// ---------------------------------------------------------------------------
__global__ void __launch_bounds__(256) pre_k(
    const float* __restrict__ x, const int* __restrict__ batch_raw,
    const float* __restrict__ vp, const float* __restrict__ W1,
    const float* __restrict__ b1, const int* __restrict__ ei, int N, int G)
{
    __shared__ float sW1[48 * 8];
    __shared__ float svp[64 * 16];
    __shared__ float sb1[8];
    __shared__ int sflag;
    int t = threadIdx.x;
    if (t == 0) sflag = detect_is64(ei);
    for (int i = t; i < 384; i += blockDim.x) sW1[i] = W1[i];
    int gv = G * 16; if (gv > 1024) gv = 1024;
    for (int i = t; i < gv; i += blockDim.x) svp[i] = vp[i];
    if (t < 8) sb1[t] = b1[t];
    __syncthreads();

    int n = blockIdx.x * blockDim.x + t;
    if (n >= N) return;

    int g = sflag ? batch_raw[2 * n] : batch_raw[n];

    float xi[16];
    const float* xr = x + (size_t)n * 16;
#pragma unroll
    for (int k = 0; k < 16; k += 4) {
        float4 v = *(const float4*)(xr + k);
        xi[k] = v.x; xi[k + 1] = v.y; xi[k + 2] = v.z; xi[k + 3] = v.w;
    }
    const float* vg = svp + g * 16;

    float xs[8], xb[8];
#pragma unroll
    for (int j = 0; j < 8; j++) {
        float a = sb1[j];
        float b = 0.0f;
#pragma unroll
        for (int k = 0; k < 16; k++) {
            a = fmaf(xi[k], sW1[k * 8 + j], a);
            a = fmaf(vg[k], sW1[(32 + k) * 8 + j], a);
            b = fmaf(xi[k], sW1[(16 + k) * 8 + j], b);
        }
        xs[j] = a; xb[j] = b;
    }
    float ms = 0.0f, mb = 0.0f;
#pragma unroll
    for (int j = 0; j < 8; j++) { ms += xs[j]; mb += xb[j]; }
    ms *= 0.125f; mb *= 0.125f;
#pragma unroll
    for (int j = 0; j < 8; j++) { xs[j] -= ms; xb[j] -= mb; }

    float4* o1 = (float4*)(g_xs + (size_t)n * 8);
    o1[0] = make_float4(xs[0], xs[1], xs[2], xs[3]);
    o1[1] = make_float4(xs[4], xs[5], xs[6], xs[7]);
    float4* o2 = (float4*)(g_xb + (size_t)n * 8);
    o2[0] = make_float4(xb[0], xb[1], xb[2], xb[3]);
    o2[1] = make_float4(xb[4], xb[5], xb[6], xb[7]);
}

// ---------------------------------------------------------------------------
// tanh pieces: z2 = 2*log2(e)*z ; rc = rcp(ex2(z2)+1) ; tanh = 1 - 2*rc
// ---------------------------------------------------------------------------
__device__ __forceinline__ float rc_from_z2(float z2) {
    float q, rc;
    asm("ex2.approx.f32 %0, %1;" : "=f"(q) : "f"(z2));
    float sum = q + 1.0f;
    asm("rcp.approx.f32 %0, %1;" : "=f"(rc) : "f"(sum));
    return rc;
}
__device__ __forceinline__ float tanh_from_z2(float z2) {
    return fmaf(-2.0f, rc_from_z2(z2), 1.0f);
}

// Mean-free LN scale (zero channel-mean inputs by construction).
__device__ __forceinline__ float ln_P(const float h[8]) {
    float q0 = fmaf(h[1], h[1], h[0] * h[0]);
    float q1 = fmaf(h[3], h[3], h[2] * h[2]);
    float q2 = fmaf(h[5], h[5], h[4] * h[4]);
    float q3 = fmaf(h[7], h[7], h[6] * h[6]);
    float ss = (q0 + q1) + (q2 + q3);
    return rsqrtf(fmaf(ss, 0.125f, 1e-5f)) * KLOG2E;
}

__device__ __forceinline__ void ln_tanh_u(float h[8]) {
    float P = ln_P(h);
#pragma unroll
    for (int j = 0; j < 8; j++) h[j] = tanh_from_z2(h[j] * P);
}
__device__ __forceinline__ void ln_tanh_g(float h[8], const float* __restrict__ g,
                                          const float* __restrict__ kbe) {
    float P = ln_P(h);
#pragma unroll
    for (int j = 0; j < 8; j++)
        h[j] = tanh_from_z2(fmaf(h[j], P * g[j], kbe[j]));
}
__device__ __forceinline__ void ln_rc_u(float h[8]) {
    float P = ln_P(h);
#pragma unroll
    for (int j = 0; j < 8; j++) h[j] = rc_from_z2(h[j] * P);
}
__device__ __forceinline__ void ln_rc_g(float h[8], const float* __restrict__ g,
                                        const float* __restrict__ kbe) {
    float P = ln_P(h);
#pragma unroll
    for (int j = 0; j < 8; j++)
        h[j] = rc_from_z2(fmaf(h[j], P * g[j], kbe[j]));
}

__device__ __forceinline__ void gemm8(const float hin[8], float hout[8],
                                      const float* __restrict__ W,
                                      const float* __restrict__ b) {
#pragma unroll
    for (int j = 0; j < 8; j++) {
        float a = b[j];
#pragma unroll
        for (int k = 0; k < 8; k++) a = fmaf(hin[k], W[k * 8 + j], a);
        hout[j] = a;
    }
}

__device__ __forceinline__ void load_idx(
    const int* __restrict__ ei, size_t E, int e0, int is64,
    int& s0, int& s1, int& d0, int& d1)
{
    if (is64) {
        int4 sw = *(const int4*)(ei + 2 * (size_t)e0);
        int4 dw = *(const int4*)(ei + 2 * (E + (size_t)e0));
        s0 = sw.x; s1 = sw.z; d0 = dw.x; d1 = dw.z;
    } else {
        int2 sw = *(const int2*)(ei + e0);
        int2 dw = *(const int2*)(ei + E + (size_t)e0);
        s0 = sw.x; s1 = sw.y; d0 = dw.x; d1 = dw.y;
    }
}

// Gather 4 node records with 256-bit loads (one LDG.256 per record).
__device__ __forceinline__ void load_recs(
    int s0, int d0, int s1, int d1,
    float4& As0, float4& As1, float4& Ab0, float4& Ab1,
    float4& Bs0, float4& Bs1, float4& Bb0, float4& Bb1)
{
    ldg256(g_xs + (size_t)s0 * 8, As0, As1);
    ldg256(g_xb + (size_t)d0 * 8, Ab0, Ab1);
    ldg256(g_xs + (size_t)s1 * 8, Bs0, Bs1);
    ldg256(g_xb + (size_t)d1 * 8, Bb0, Bb1);
}

__global__ void __launch_bounds__(128, 4) edge_k(
    const int* __restrict__ ei, int E,
    const float* __restrict__ g1, const float* __restrict__ be1,
    const float* __restrict__ W2, const float* __restrict__ b2,
    const float* __restrict__ g2, const float* __restrict__ be2,
    const float* __restrict__ W3, const float* __restrict__ b3,
    const float* __restrict__ g3, const float* __restrict__ be3,
    const float* __restrict__ W4, const float* __restrict__ b4,
    float* __restrict__ out)
{
    __shared__ float sW2[64], sW3[64], sW4[8];
    __shared__ float sv[64];
    __shared__ float sW4sum;
    __shared__ int sflag, suni;
    int t = threadIdx.x;
    if (t == 0) {
        sflag = detect_is64(ei);
        float ssum = b4[0];
#pragma unroll
        for (int j = 0; j < 8; j++) ssum += W4[j];
        sW4sum = ssum;
        int u = 1;
#pragma unroll
        for (int j = 0; j < 8; j++) {
            u &= (g1[j] == 1.0f) & (be1[j] == 0.0f);
            u &= (g2[j] == 1.0f) & (be2[j] == 0.0f);
            u &= (g3[j] == 1.0f) & (be3[j] == 0.0f);
        }
        suni = u;
    }
    // Channel-centered weights (mean-free LN).
    if (t < 64) {
        int row = t >> 3;
        float m2 = 0.0f, m3 = 0.0f;
#pragma unroll
        for (int j = 0; j < 8; j++) { m2 += W2[row * 8 + j]; m3 += W3[row * 8 + j]; }
        sW2[t] = W2[t] - m2 * 0.125f;
        sW3[t] = W3[t] - m3 * 0.125f;
    }
    if (t < 8) {
        sW4[t] = W4[t];
        float mb2 = 0.0f, mb3 = 0.0f;
#pragma unroll
        for (int j = 0; j < 8; j++) { mb2 += b2[j]; mb3 += b3[j]; }
        sv[t]      = g1[t];  sv[8 + t]  = KLOG2E * be1[t];
        sv[16 + t] = b2[t] - mb2 * 0.125f;
        sv[24 + t] = g2[t];  sv[32 + t] = KLOG2E * be2[t];
        sv[40 + t] = b3[t] - mb3 * 0.125f;
        sv[48 + t] = g3[t];  sv[56 + t] = KLOG2E * be3[t];
    }
    __syncthreads();

    const float* sg1 = sv;       const float* skb1 = sv + 8;
    const float* sb2 = sv + 16;  const float* sg2  = sv + 24; const float* skb2 = sv + 32;
    const float* sb3 = sv + 40;  const float* sg3  = sv + 48; const float* skb3 = sv + 56;

    const int is64 = sflag;
    const int uni  = suni;
    const float w4sum = sW4sum;
    const int stride2 = gridDim.x * blockDim.x * 2;
    const int eSafe = (E >= 2) ? (E - 2) : 0;

    int e = (blockIdx.x * blockDim.x + t) * 2;

    // ping-pong state
    float4 A0s0, A0s1, A0b0, A0b1, B0s0, B0s1, B0b0, B0b1;   // buffer 0
    float4 A1s0, A1s1, A1b0, A1b1, B1s0, B1s1, B1b0, B1b1;   // buffer 1
    int i0s0 = 0, i0s1 = 0, i0d0 = 0, i0d1 = 0;              // index set 0
    int i1s0 = 0, i1s1 = 0, i1d0 = 0, i1d1 = 0;              // index set 1

    if (e >= E) return;

    // prologue: records for e into buf0; indices for e+stride2 into set1
    {
        int s0, s1, d0, d1;
        int ec = e <= eSafe ? e : eSafe;
        load_idx(ei, (size_t)E, ec, is64, s0, s1, d0, d1);
        load_recs(s0, d0, s1, d1, A0s0, A0s1, A0b0, A0b1, B0s0, B0s1, B0b0, B0b1);
        int en = e + stride2;
        if (en < E) {
            int enc = en <= eSafe ? en : eSafe;
            load_idx(ei, (size_t)E, enc, is64, i1s0, i1s1, i1d0, i1d1);
        }
    }

    // one pipeline step: gathers NEXT records from IDXN into NBUF, prefetches
    // indices 2 ahead into IDXN (consumed), computes on CBUF, stores, advances.
#define PIPE_STEP(Cs0,Cs1,Cb0,Cb1,Ds0,Ds1,Db0,Db1,  /* current buf */         \
                  Ns0,Ns1,Nb0,Nb1,Ms0,Ms1,Mb0,Mb1,  /* next buf */            \
                  IS0,IS1,ID0,ID1)                  /* idx set for next */    \
    {                                                                          \
        int en = e + stride2;                                                  \
        bool nv = (en < E);                                                    \
        if (nv)                                                                \
            load_recs(IS0, ID0, IS1, ID1,                                      \
                      Ns0, Ns1, Nb0, Nb1, Ms0, Ms1, Mb0, Mb1);                 \
        int en2 = en + stride2;                                                \
        if (en2 < E) {                                                         \
            int ec2 = en2 <= eSafe ? en2 : eSafe;                              \
            load_idx(ei, (size_t)E, ec2, is64, IS0, IS1, ID0, ID1);            \
        }                                                                      \
        float hA[8] = { Cs0.x + Cb0.x, Cs0.y + Cb0.y, Cs0.z + Cb0.z,           \
                        Cs0.w + Cb0.w, Cs1.x + Cb1.x, Cs1.y + Cb1.y,           \
                        Cs1.z + Cb1.z, Cs1.w + Cb1.w };                        \
        float hB[8] = { Ds0.x + Db0.x, Ds0.y + Db0.y, Ds0.z + Db0.z,           \
                        Ds0.w + Db0.w, Ds1.x + Db1.x, Ds1.y + Db1.y,           \
                        Ds1.z + Db1.z, Ds1.w + Db1.w };                        \
        float h2A[8], h2B[8], h3A[8], h3B[8];                                  \
        if (uni) {                                                             \
            ln_tanh_u(hA);                    ln_tanh_u(hB);                   \
            gemm8(hA, h2A, sW2, sb2);         gemm8(hB, h2B, sW2, sb2);        \
            ln_tanh_u(h2A);                   ln_tanh_u(h2B);                  \
            gemm8(h2A, h3A, sW3, sb3);        gemm8(h2B, h3B, sW3, sb3);       \
            ln_rc_u(h3A);                     ln_rc_u(h3B);                    \
        } else {                                                               \
            ln_tanh_g(hA, sg1, skb1);         ln_tanh_g(hB, sg1, skb1);        \
            gemm8(hA, h2A, sW2, sb2);         gemm8(hB, h2B, sW2, sb2);        \
            ln_tanh_g(h2A, sg2, skb2);        ln_tanh_g(h2B, sg2, skb2);       \
            gemm8(h2A, h3A, sW3, sb3);        gemm8(h2B, h3B, sW3, sb3);       \
            ln_rc_g(h3A, sg3, skb3);          ln_rc_g(h3B, sg3, skb3);         \
        }                                                                      \
        float dA = 0.0f, dB = 0.0f;                                            \
        _Pragma("unroll")                                                      \
        for (int k = 0; k < 8; k++) {                                          \
            float w = sW4[k];                                                  \
            dA = fmaf(h3A[k], w, dA);                                          \
            dB = fmaf(h3B[k], w, dB);                                          \
        }                                                                      \
        float oA = fmaf(-2.0f, dA, w4sum);                                     \
        float oB = fmaf(-2.0f, dB, w4sum);                                     \
        if (e + 1 < E) *(float2*)(out + e) = make_float2(oA, oB);              \
        else           out[e] = oA;                                           \
        if (!nv) return;                                                      \
        e = en;                                                                \
    }

    for (;;) {
        // step A: compute buf0, fill buf1 from idx set1, refill set1 with e+2
        PIPE_STEP(A0s0, A0s1, A0b0, A0b1, B0s0, B0s1, B0b0, B0b1,
                  A1s0, A1s1, A1b0, A1b1, B1s0, B1s1, B1b0, B1b1,
                  i1s0, i1s1, i1d0, i1d1)
        // step B: compute buf1, fill buf0 from idx set1 (just refilled), refill
        PIPE_STEP(A1s0, A1s1, A1b0, A1b1, B1s0, B1s1, B1b0, B1b1,
                  A0s0, A0s1, A0b0, A0b1, B0s0, B0s1, B0b0, B0b1,
                  i1s0, i1s1, i1d0, i1d1)
    }
#undef PIPE_STEP
}

// ---------------------------------------------------------------------------
extern "C" void kernel_launch(void* const* d_in, const int* in_sizes, int n_in,
                              void* d_out, int out_size)
{
    const float* x     = (const float*)d_in[0];
    const int*   ei    = (const int*)d_in[1];
    const float* vp    = (const float*)d_in[2];
    const int*   batch = (const int*)d_in[3];
    const float* W1  = (const float*)d_in[4];
    const float* b1  = (const float*)d_in[5];
    const float* g1  = (const float*)d_in[6];
    const float* be1 = (const float*)d_in[7];
    const float* W2  = (const float*)d_in[8];
    const float* b2  = (const float*)d_in[9];
    const float* g2  = (const float*)d_in[10];
    const float* be2 = (const float*)d_in[11];
    const float* W3  = (const float*)d_in[12];
    const float* b3  = (const float*)d_in[13];
    const float* g3  = (const float*)d_in[14];
    const float* be3 = (const float*)d_in[15];
    const float* W4  = (const float*)d_in[16];
    const float* b4  = (const float*)d_in[17];

    int N = in_sizes[0] / 16;
    int E = in_sizes[1] / 2;
    int G = in_sizes[2] / 16;

    int pb = (N + 255) / 256;
    pre_k<<<pb, 256>>>(x, batch, vp, W1, b1, ei, N, G);

    // persistent 1-wave grid: 4 blocks/SM x 148 SMs = 16 warps/SM
    int eb = 592;
    long long need = ((long long)E / 2 + 127) / 128;
    if (need < eb) eb = (int)(need > 0 ? need : 1);
    edge_k<<<eb, 128>>>(ei, E, g1, be1, W2, b2, g2, be2, W3, b3, g3, be3,
                        W4, b4, (float*)d_out);
}